// round 7
// baseline (speedup 1.0000x reference)
#include <cuda_runtime.h>
#include <math.h>

#define FULL 0xffffffffu

// ---------------------------------------------------------------------------
// Closed form (verified rounds 1-6): fold the trailing CNOT ring into the
// PauliZ masks; the measured state is a product state, so
//   <Z_w> = prod_{q in M_w} z_q,  M_w = {0..w} (w>=1), M_0 = {1..9}
//   RX-circuit: z = cos(h + theta) ; RY-circuit: z = cos(theta)*cos(h)
//
// Layout: 8 threads/row octet, TWO rows per thread (W loads amortized,
// doubled ILP on every latency chain), 8 rows/warp, 512 blocks x 128 thr.
// Weight trig + bias precomputed into g_tab by a setup kernel.
// ---------------------------------------------------------------------------

__device__ float4 g_tab[10][2];   // [w][0] = (b, cos wf, sin wf, cos wi)
                                  // [w][1] = (cos wu, sin wu, cos wo, sin wo)

__global__ void setup_kernel(const float* __restrict__ b,
                             const float* __restrict__ wf,
                             const float* __restrict__ wi,
                             const float* __restrict__ wu,
                             const float* __restrict__ wo) {
    int w = threadIdx.x;
    if (w < 10) {
        float sf, cf, su, cu, so, co;
        sincosf(wf[w], &sf, &cf);
        sincosf(wu[w], &su, &cu);
        sincosf(wo[w], &so, &co);
        g_tab[w][0] = make_float4(b[w], cf, sf, cosf(wi[w]));
        g_tab[w][1] = make_float4(cu, su, co, so);
    }
}

// Per-row epilogue: quad lane q owns wires {3q,3q+1,3q+2} (q=3: wire 9).
// Only the low quad of each octet stores.
__device__ __forceinline__ void epilogue(const float (&acc)[10], int lane,
                                         int row, bool writer,
                                         float* __restrict__ out) {
    const int q = lane & 3;
    const int nw = (q < 3) ? 3 : 1;
    const int w0 = 3 * q;

    float myh[3], zf[3], zi[3], zu[3], zo[3];
#pragma unroll
    for (int j = 0; j < 3; j++) {
        float hv = acc[j];
        if (q == 1) hv = acc[3 + j];
        if (q == 2) hv = acc[6 + j];
        if (q == 3) hv = (j == 0) ? acc[9] : 0.0f;

        if (j < nw) {
            const int w = w0 + j;
            const float4 t0 = g_tab[w][0];
            const float4 t1 = g_tab[w][1];
            const float h = hv + t0.x;
            myh[j] = h;
            float sh, ch;
            __sincosf(h, &sh, &ch);
            zf[j] = ch * t0.y - sh * t0.z;     // cos(h + wf)
            zi[j] = t0.w * ch;                 // cos(wi) * cos(h)
            zu[j] = ch * t1.x - sh * t1.y;
            zo[j] = ch * t1.z - sh * t1.w;
        } else {
            myh[j] = 0.0f;
            zf[j] = zi[j] = zu[j] = zo[j] = 1.0f;
        }
    }

    // Per-circuit quad prefix products via 3-shfl xor-gather.
    // l3 = z0*z1*z2 of this lane; x1 = l3(q^1), x2 = l3(q^2), x3 = l3(q^3).
    // C(q) = prod_{q'<q} l3(q') = {1, x1, x2*x3, x1*x2*x3}[q];
    // wire-0 suffix (q==0 only) = l3(1)*l3(2)*l3(3) = x1*x2*x3 (same p123).
    const int q2 = q;
    float Ef[3], Ei[3], Eu[3], Eo[3];
#pragma unroll
    for (int c = 0; c < 4; c++) {
        const float* z = (c == 0) ? zf : (c == 1) ? zi : (c == 2) ? zu : zo;
        const float l1 = z[0], l2 = l1 * z[1], l3 = l2 * z[2];

        const float x1 = __shfl_xor_sync(FULL, l3, 1);
        const float x2 = __shfl_xor_sync(FULL, l3, 2);
        const float x3 = __shfl_xor_sync(FULL, x1, 2);
        const float p23  = x2 * x3;
        const float p123 = x1 * p23;
        float C = (q2 == 0) ? 1.0f : (q2 == 1) ? x1 : (q2 == 2) ? p23 : p123;

        float E0 = C * l1;
        if (q2 == 0) E0 = z[1] * z[2] * p123;          // wire 0: z1..z9
        const float E1 = C * l2, E2 = C * l3;

        if (c == 0)      { Ef[0] = E0; Ef[1] = E1; Ef[2] = E2; }
        else if (c == 1) { Ei[0] = E0; Ei[1] = E1; Ei[2] = E2; }
        else if (c == 2) { Eu[0] = E0; Eu[1] = E1; Eu[2] = E2; }
        else             { Eo[0] = E0; Eo[1] = E1; Eo[2] = E2; }
    }

#pragma unroll
    for (int j = 0; j < 3; j++) {
        if (j < nw && writer) {
            const float ing = __fdividef(1.0f, 1.0f + __expf(-Ef[j]));
            const float fg  = __fdividef(1.0f, 1.0f + __expf(-Ei[j]));
            const float cg  = __fdividef(2.0f, 1.0f + __expf(-2.0f * Eu[j])) - 1.0f;
            const float og  = __fdividef(1.0f, 1.0f + __expf(-Eo[j]));
            const float nh  = fmaf(myh[j], fg, ing * cg);
            const float th  = __fdividef(2.0f, 1.0f + __expf(-2.0f * nh)) - 1.0f;
            out[row * 10 + w0 + j] = og * th;
        }
    }
}

__global__ void __launch_bounds__(128)
qlstm_kernel(const float* __restrict__ x, const float* __restrict__ W,
             float* __restrict__ out) {
    const int tid = threadIdx.x;
    const int oc  = tid & 7;                       // eighth within row
    const int g   = (blockIdx.x * 128 + tid) >> 3; // octet index
    const int r0  = 2 * g, r1 = 2 * g + 1;

    // ---- front-batched x loads for both rows (MLP = 8) ----
    const float4* x40 = reinterpret_cast<const float4*>(x) + (size_t)r0 * 32;
    const float4* x41 = reinterpret_cast<const float4*>(x) + (size_t)r1 * 32;
    float4 xa[4], xb[4];
#pragma unroll
    for (int i = 0; i < 4; i++) xa[i] = __ldcs(&x40[i * 8 + oc]);
#pragma unroll
    for (int i = 0; i < 4; i++) xb[i] = __ldcs(&x41[i * 8 + oc]);

    // ---- GEMM for both rows; each W load feeds two FMA chains ----
    const float4* W4 = reinterpret_cast<const float4*>(W);
    float a0[10], a1[10];
#pragma unroll
    for (int o = 0; o < 10; o++) { a0[o] = 0.0f; a1[o] = 0.0f; }
#pragma unroll
    for (int i = 0; i < 4; i++) {
#pragma unroll
        for (int o = 0; o < 10; o++) {
            const float4 wv = __ldg(&W4[o * 32 + i * 8 + oc]);
            a0[o] = fmaf(xa[i].x, wv.x, fmaf(xa[i].y, wv.y,
                    fmaf(xa[i].z, wv.z, fmaf(xa[i].w, wv.w, a0[o]))));
            a1[o] = fmaf(xb[i].x, wv.x, fmaf(xb[i].y, wv.y,
                    fmaf(xb[i].z, wv.z, fmaf(xb[i].w, wv.w, a1[o]))));
        }
    }
    // octet allreduce, two independent chains interleaved
#pragma unroll
    for (int o = 0; o < 10; o++) {
        a0[o] += __shfl_xor_sync(FULL, a0[o], 1);
        a1[o] += __shfl_xor_sync(FULL, a1[o], 1);
        a0[o] += __shfl_xor_sync(FULL, a0[o], 2);
        a1[o] += __shfl_xor_sync(FULL, a1[o], 2);
        a0[o] += __shfl_xor_sync(FULL, a0[o], 4);
        a1[o] += __shfl_xor_sync(FULL, a1[o], 4);
    }

    const int lane = tid & 31;
    const bool writer = (lane & 4) == 0;
    epilogue(a0, lane, r0, writer, out);
    epilogue(a1, lane, r1, writer, out);
}

extern "C" void kernel_launch(void* const* d_in, const int* in_sizes, int n_in,
                              void* d_out, int out_size) {
    const float* x  = (const float*)d_in[0];
    const float* W  = (const float*)d_in[1];
    const float* b  = (const float*)d_in[2];
    const float* wf = (const float*)d_in[3];
    const float* wi = (const float*)d_in[4];
    const float* wu = (const float*)d_in[5];
    const float* wo = (const float*)d_in[6];
    float* out = (float*)d_out;

    setup_kernel<<<1, 32>>>(b, wf, wi, wu, wo);
    // 16384 rows / 2 per thread * 8 thr/row = 65536 threads -> 512 blocks
    qlstm_kernel<<<512, 128>>>(x, W, out);
}

// round 9
// speedup vs baseline: 1.1994x; 1.1994x over previous
#include <cuda_runtime.h>
#include <math.h>

#define FULL 0xffffffffu

// ---------------------------------------------------------------------------
// Closed form (verified rounds 1-7): fold the trailing CNOT ring into the
// PauliZ masks; the measured state is a product state, so
//   <Z_w> = prod_{q in M_w} z_q,  M_w = {0..w} (w>=1), M_0 = {1..9}
//   RX-circuit: z = cos(h + theta) ; RY-circuit: z = cos(theta)*cos(h)
//
// Layout (= round-6 best, 131072 threads): 8 threads/row octet, 1 row/thread,
// 4 rows/warp, 1024 blocks x 128 threads, single kernel launch.
// GEMM uses packed fma.rn.f32x2: LDG.128 payloads consumed directly as
// 64-bit f32x2 register pairs -> 80 packed FMA instead of 160 scalar FFMA.
// (R8 bug fixed: x row stride is 32 sixteen-byte granules, not 16.)
// ---------------------------------------------------------------------------

__device__ __forceinline__ unsigned long long
fma_f32x2(unsigned long long a, unsigned long long bb, unsigned long long c) {
    unsigned long long d;
    asm("fma.rn.f32x2 %0, %1, %2, %3;" : "=l"(d) : "l"(a), "l"(bb), "l"(c));
    return d;
}

__global__ void __launch_bounds__(128)
qlstm_kernel(const float* __restrict__ x, const float* __restrict__ W,
             const float* __restrict__ b,
             const float* __restrict__ wf, const float* __restrict__ wi,
             const float* __restrict__ wu, const float* __restrict__ wo,
             float* __restrict__ out) {
    const int tid = threadIdx.x;
    const int oc  = tid & 7;                   // eighth within row
    const int row = (blockIdx.x * 128 + tid) >> 3;

    // ---- front-batched streaming x loads: row = 32 x 16B granules ----
    const longlong2* xp = reinterpret_cast<const longlong2*>(x) + (size_t)row * 32;
    longlong2 xv[4];
#pragma unroll
    for (int i = 0; i < 4; i++) xv[i] = __ldcs(&xp[i * 8 + oc]);

    // ---- GEMM: h = x[row] @ W^T, packed f32x2 FMA ----
    const longlong2* Wp = reinterpret_cast<const longlong2*>(W);
    unsigned long long acc2[10];
#pragma unroll
    for (int o = 0; o < 10; o++) acc2[o] = 0ull;   // f32x2 (+0,+0)
#pragma unroll
    for (int i = 0; i < 4; i++) {
        const unsigned long long xlo = (unsigned long long)xv[i].x;
        const unsigned long long xhi = (unsigned long long)xv[i].y;
#pragma unroll
        for (int o = 0; o < 10; o++) {
            const longlong2 wv = __ldg(&Wp[o * 32 + i * 8 + oc]);
            acc2[o] = fma_f32x2(xlo, (unsigned long long)wv.x, acc2[o]);
            acc2[o] = fma_f32x2(xhi, (unsigned long long)wv.y, acc2[o]);
        }
    }
    float acc[10];
#pragma unroll
    for (int o = 0; o < 10; o++) {
        const float lo = __uint_as_float((unsigned)(acc2[o] & 0xffffffffull));
        const float hi = __uint_as_float((unsigned)(acc2[o] >> 32));
        acc[o] = lo + hi;
    }
    // octet allreduce: all 8 lanes end with the full sums
#pragma unroll
    for (int o = 0; o < 10; o++) {
        acc[o] += __shfl_xor_sync(FULL, acc[o], 1);
        acc[o] += __shfl_xor_sync(FULL, acc[o], 2);
        acc[o] += __shfl_xor_sync(FULL, acc[o], 4);
    }

    // ---- quad-wide epilogue (both quads of the octet run it identically) --
    const int lane = tid & 31;
    const int q = lane & 3;
    const int nw = (q < 3) ? 3 : 1;
    const int w0 = 3 * q;

    float myh[3], zf[3], zi[3], zu[3], zo[3];
#pragma unroll
    for (int j = 0; j < 3; j++) {
        float hv = acc[j];
        if (q == 1) hv = acc[3 + j];
        if (q == 2) hv = acc[6 + j];
        if (q == 3) hv = (j == 0) ? acc[9] : 0.0f;

        if (j < nw) {
            const int w = w0 + j;
            const float h = hv + __ldg(b + w);
            myh[j] = h;
            const float ch = __cosf(h);
            zf[j] = __cosf(h + __ldg(wf + w));          // RX: cos(h + wf)
            zi[j] = __cosf(__ldg(wi + w)) * ch;         // RY: cos(wi)*cos(h)
            zu[j] = __cosf(h + __ldg(wu + w));
            zo[j] = __cosf(h + __ldg(wo + w));
        } else {
            myh[j] = 0.0f;
            zf[j] = zi[j] = zu[j] = zo[j] = 1.0f;
        }
    }

    // per-circuit quad prefix products via 3-shfl xor-gather
    float Ef[3], Ei[3], Eu[3], Eo[3];
#pragma unroll
    for (int c = 0; c < 4; c++) {
        const float* z = (c == 0) ? zf : (c == 1) ? zi : (c == 2) ? zu : zo;
        const float l1 = z[0], l2 = l1 * z[1], l3 = l2 * z[2];

        const float x1 = __shfl_xor_sync(FULL, l3, 1);
        const float x2 = __shfl_xor_sync(FULL, l3, 2);
        const float x3 = __shfl_xor_sync(FULL, x1, 2);
        const float p23  = x2 * x3;
        const float p123 = x1 * p23;
        const float C = (q == 0) ? 1.0f : (q == 1) ? x1 : (q == 2) ? p23 : p123;

        float E0 = C * l1;
        if (q == 0) E0 = z[1] * z[2] * p123;            // wire 0: z1..z9
        const float E1 = C * l2, E2 = C * l3;

        if (c == 0)      { Ef[0] = E0; Ef[1] = E1; Ef[2] = E2; }
        else if (c == 1) { Ei[0] = E0; Ei[1] = E1; Ei[2] = E2; }
        else if (c == 2) { Eu[0] = E0; Eu[1] = E1; Eu[2] = E2; }
        else             { Eo[0] = E0; Eo[1] = E1; Eo[2] = E2; }
    }

    // ---- LSTM epilogue; only the low quad of each octet stores ----
    const bool writer = (lane & 4) == 0;
#pragma unroll
    for (int j = 0; j < 3; j++) {
        if (j < nw && writer) {
            const float ing = __fdividef(1.0f, 1.0f + __expf(-Ef[j]));
            const float fg  = __fdividef(1.0f, 1.0f + __expf(-Ei[j]));
            const float cg  = __fdividef(2.0f, 1.0f + __expf(-2.0f * Eu[j])) - 1.0f;
            const float og  = __fdividef(1.0f, 1.0f + __expf(-Eo[j]));
            const float nh  = fmaf(myh[j], fg, ing * cg);
            const float th  = __fdividef(2.0f, 1.0f + __expf(-2.0f * nh)) - 1.0f;
            out[row * 10 + w0 + j] = og * th;
        }
    }
}

extern "C" void kernel_launch(void* const* d_in, const int* in_sizes, int n_in,
                              void* d_out, int out_size) {
    const float* x  = (const float*)d_in[0];
    const float* W  = (const float*)d_in[1];
    const float* b  = (const float*)d_in[2];
    const float* wf = (const float*)d_in[3];
    const float* wi = (const float*)d_in[4];
    const float* wu = (const float*)d_in[5];
    const float* wo = (const float*)d_in[6];
    float* out = (float*)d_out;

    // 16384 rows x 8 threads = 131072 threads; 128/block -> 1024 blocks
    qlstm_kernel<<<1024, 128>>>(x, W, b, wf, wi, wu, wo, out);
}